// round 13
// baseline (speedup 1.0000x reference)
#include <cuda_runtime.h>
#include <cstdint>

#define VOCAB 50257
#define SLEN  2048
#define BATCH 64
#define HDIM  300
#define HPAD  304
#define HALF  150
#define GCHUNK 76            // HPAD / 4 column-groups
#define NJ    19             // GCHUNK / 4 float4s per thread
#define NPAIR 75             // 150 rows = 75 pairs per CTA
#define RNN_THREADS 320      // 10 warps x 8 pair-slots = 80 >= 75
#define NWARPS 10

// Scratch (device globals are the sanctioned allocation-free scratch).
__device__ float g_proj[(size_t)VOCAB * HDIM];   // ~60.3 MB
__device__ float g_pooled[SLEN * HDIM];

// ---------------------------------------------------------------------------
// packed f32x2 helpers (FFMA2 — only reachable via PTX on sm_103a)
// ---------------------------------------------------------------------------
__device__ __forceinline__ unsigned long long fma2(unsigned long long a,
                                                   unsigned long long b,
                                                   unsigned long long c) {
    unsigned long long d;
    asm("fma.rn.f32x2 %0, %1, %2, %3;" : "=l"(d) : "l"(a), "l"(b), "l"(c));
    return d;
}
__device__ __forceinline__ unsigned long long dup2(float a) {
    unsigned long long d;
    asm("mov.b64 %0, {%1, %1};" : "=l"(d) : "f"(a));
    return d;
}

// ---------------------------------------------------------------------------
// Kernel 0: zero the pooled max buffer (graph replays must re-zero it)
// ---------------------------------------------------------------------------
__global__ void zero_pooled_kernel() {
    int idx = blockIdx.x * blockDim.x + threadIdx.x;
    if (idx < SLEN * HDIM) g_pooled[idx] = 0.f;
}

// ---------------------------------------------------------------------------
// Kernel 1: proj[v, i] = sum_k emb[v,k] * W_ih[i,k] + b_ih[i] + b_hh[i]
// 64x64 tiled fp32 GEMM, 4x4 micro-tiles via packed f32x2 FMA, KC=16.
// ---------------------------------------------------------------------------
#define PK_KC 16
__global__ void __launch_bounds__(256)
proj_kernel(const float* __restrict__ emb, const float* __restrict__ W_ih,
            const float* __restrict__ b_ih, const float* __restrict__ b_hh)
{
    __shared__ float sA[PK_KC][68];   // [k][m]  (emb tile, transposed)
    __shared__ float sB[PK_KC][68];   // [k][n]  (W_ih tile, transposed)

    const int tid = threadIdx.x;
    const int tx = tid & 15;
    const int ty = tid >> 4;
    const int m0 = blockIdx.x * 64;
    const int n0 = blockIdx.y * 64;

    const int e  = tid * 4;      // each thread loads one float4 per tile
    const int lm = e >> 4;       // 0..63
    const int lk = e & 15;       // 0,4,8,12

    unsigned long long acc2[4][2] = {};

    for (int k0 = 0; k0 < HDIM; k0 += PK_KC) {
        // load A tile (emb rows m0..m0+63)
        {
            int m = m0 + lm;
            int k = k0 + lk;
            float4 v = make_float4(0.f, 0.f, 0.f, 0.f);
            if (m < VOCAB) {
                if (k + 3 < HDIM) {
                    v = *reinterpret_cast<const float4*>(&emb[(size_t)m * HDIM + k]);
                } else {
                    float t0 = (k     < HDIM) ? emb[(size_t)m * HDIM + k    ] : 0.f;
                    float t1 = (k + 1 < HDIM) ? emb[(size_t)m * HDIM + k + 1] : 0.f;
                    float t2 = (k + 2 < HDIM) ? emb[(size_t)m * HDIM + k + 2] : 0.f;
                    float t3 = (k + 3 < HDIM) ? emb[(size_t)m * HDIM + k + 3] : 0.f;
                    v = make_float4(t0, t1, t2, t3);
                }
            }
            sA[lk    ][lm] = v.x;
            sA[lk + 1][lm] = v.y;
            sA[lk + 2][lm] = v.z;
            sA[lk + 3][lm] = v.w;
        }
        // load B tile (W_ih rows n0..n0+63)
        {
            int n = n0 + lm;
            int k = k0 + lk;
            float4 v = make_float4(0.f, 0.f, 0.f, 0.f);
            if (n < HDIM) {
                if (k + 3 < HDIM) {
                    v = *reinterpret_cast<const float4*>(&W_ih[n * HDIM + k]);
                } else {
                    float t0 = (k     < HDIM) ? W_ih[n * HDIM + k    ] : 0.f;
                    float t1 = (k + 1 < HDIM) ? W_ih[n * HDIM + k + 1] : 0.f;
                    float t2 = (k + 2 < HDIM) ? W_ih[n * HDIM + k + 2] : 0.f;
                    float t3 = (k + 3 < HDIM) ? W_ih[n * HDIM + k + 3] : 0.f;
                    v = make_float4(t0, t1, t2, t3);
                }
            }
            sB[lk    ][lm] = v.x;
            sB[lk + 1][lm] = v.y;
            sB[lk + 2][lm] = v.z;
            sB[lk + 3][lm] = v.w;
        }
        __syncthreads();

        #pragma unroll
        for (int kk = 0; kk < PK_KC; kk++) {
            float4 a4 = *reinterpret_cast<const float4*>(&sA[kk][ty * 4]);
            ulonglong2 b2 = *reinterpret_cast<const ulonglong2*>(&sB[kk][tx * 4]);
            float av[4] = {a4.x, a4.y, a4.z, a4.w};
            #pragma unroll
            for (int mi = 0; mi < 4; mi++) {
                unsigned long long am = dup2(av[mi]);
                acc2[mi][0] = fma2(am, b2.x, acc2[mi][0]);
                acc2[mi][1] = fma2(am, b2.y, acc2[mi][1]);
            }
        }
        __syncthreads();
    }

    #pragma unroll
    for (int mi = 0; mi < 4; mi++) {
        int m = m0 + ty * 4 + mi;
        if (m >= VOCAB) continue;
        float r[4];
        r[0] = __uint_as_float((uint32_t)(acc2[mi][0]));
        r[1] = __uint_as_float((uint32_t)(acc2[mi][0] >> 32));
        r[2] = __uint_as_float((uint32_t)(acc2[mi][1]));
        r[3] = __uint_as_float((uint32_t)(acc2[mi][1] >> 32));
        #pragma unroll
        for (int ni = 0; ni < 4; ni++) {
            int n = n0 + tx * 4 + ni;
            if (n < HDIM)
                g_proj[(size_t)m * HDIM + n] = r[ni] + b_ih[n] + b_hh[n];
        }
    }
}

// ---------------------------------------------------------------------------
// Kernel 2: the Elman recurrence — W_hh register-resident, 2 rows per thread,
// funnel sync protocol over a 2-STAGE MBARRIER RING.
//
// Why a ring: with a single 1-arrival mbarrier + parity waits, the peer can
// legally arrive twice (steps s and s+1) before this CTA's poll observes the
// first flip — two flips restore the old parity and the wait spins forever
// (this exact deadlock killed the previous revision). With mbar[s&1] and
// phase parity (s>>1)&1, a second arrival on the same barrier would require
// this CTA to have already passed its wait on it, so double-flip is
// impossible by construction.
//
// One 2-CTA cluster per batch element. Thread (warp w, lane l): column-group
// g = l>>3 (0..3), pair-slot q = l&7, pair = w*8+q (75 valid / CTA) covering
// local rows 2*pair, 2*pair+1. Each thread holds 2x76 W_hh values in
// registers and loads its 76-float h chunk ONCE per step for both rows.
// Per step: dot + 2 shfl reduces, b64 local/peer h store, bar.sync, one
// release-arrive on the peer's mbar[s&1] (from the highest warp — hi-wid-
// first arbitration schedules it first after the barrier), shadow work
// (gather prefetch + pooled atomicMax), then try_wait on local mbar[s&1].
// ---------------------------------------------------------------------------
__global__ void __launch_bounds__(RNN_THREADS, 1) __cluster_dims__(2, 1, 1)
rnn_kernel(const int* __restrict__ x, const float* __restrict__ W_hh,
           float* __restrict__ out_hid)
{
    __shared__ float hbuf[2 * HPAD];                     // double-buffered h
    __shared__ __align__(16) unsigned long long mbar[2]; // 2-stage ring, 1 arrival each

    const int tid = threadIdx.x;
    uint32_t rank;
    asm("mov.u32 %0, %%cluster_ctarank;" : "=r"(rank));
    const int batch = blockIdx.x >> 1;

    const int w = tid >> 5;
    const int l = tid & 31;
    const int g = l >> 3;            // k-group 0..3
    const int q = l & 7;             // pair-slot 0..7
    const int pair = w * 8 + q;      // 0..79 (75 valid)
    const bool valid = (pair < NPAIR);
    const int pr_use = valid ? pair : 0;
    const int r0 = 2 * pr_use;                 // local rows r0, r0+1
    const int row0 = rank * HALF + r0;         // global rows row0, row0+1

    // ---- load 2 rows x 76 W_hh values into registers (one-time) ----
    ulonglong2 wq0[NJ], wq1[NJ];
    #pragma unroll
    for (int j = 0; j < NJ; j++) {
        const int c0 = g * GCHUNK + j * 4;
        float4 v0 = make_float4(0.f, 0.f, 0.f, 0.f);
        float4 v1 = make_float4(0.f, 0.f, 0.f, 0.f);
        if (c0 < HDIM) {  // only (g==3, j==18) is out of range; rows 16B-aligned
            v0 = *reinterpret_cast<const float4*>(&W_hh[(row0    ) * HDIM + c0]);
            v1 = *reinterpret_cast<const float4*>(&W_hh[(row0 + 1) * HDIM + c0]);
        }
        wq0[j].x = ((unsigned long long)__float_as_uint(v0.y) << 32) | (unsigned long long)__float_as_uint(v0.x);
        wq0[j].y = ((unsigned long long)__float_as_uint(v0.w) << 32) | (unsigned long long)__float_as_uint(v0.z);
        wq1[j].x = ((unsigned long long)__float_as_uint(v1.y) << 32) | (unsigned long long)__float_as_uint(v1.x);
        wq1[j].y = ((unsigned long long)__float_as_uint(v1.w) << 32) | (unsigned long long)__float_as_uint(v1.z);
    }

    for (int idx = tid; idx < 2 * HPAD; idx += RNN_THREADS) hbuf[idx] = 0.f;  // h0 = 0

    // SMEM addresses (32-bit) for hbuf and the mbarrier ring.
    uint32_t hbase, mb0, mb1;
    asm("{ .reg .u64 t; cvta.to.shared.u64 t, %1; cvt.u32.u64 %0, t; }"
        : "=r"(hbase) : "l"(hbuf));
    asm("{ .reg .u64 t; cvta.to.shared.u64 t, %1; cvt.u32.u64 %0, t; }"
        : "=r"(mb0) : "l"(&mbar[0]));
    mb1 = mb0 + 8u;

    if (tid == 0) {
        asm volatile("mbarrier.init.shared.b64 [%0], 1;" :: "r"(mb0) : "memory");
        asm volatile("mbarrier.init.shared.b64 [%0], 1;" :: "r"(mb1) : "memory");
    }
    __syncthreads();
    // Both CTAs' hbuf zeros + mbarrier inits must be visible cluster-wide once.
    asm volatile("barrier.cluster.arrive.aligned;" ::: "memory");
    asm volatile("barrier.cluster.wait.aligned;"   ::: "memory");

    // Peer addresses: h pair-slots (both phases) and the peer's mbarrier ring.
    const uint32_t prk = rank ^ 1u;
    uint32_t ra[2], peer_mb[2];
    {
        uint32_t la0 = hbase + (uint32_t)row0 * 4u;             // 8B aligned (row0 even)
        uint32_t la1 = hbase + (uint32_t)(HPAD + row0) * 4u;
        asm("mapa.shared::cluster.u32 %0, %1, %2;" : "=r"(ra[0]) : "r"(la0), "r"(prk));
        asm("mapa.shared::cluster.u32 %0, %1, %2;" : "=r"(ra[1]) : "r"(la1), "r"(prk));
        asm("mapa.shared::cluster.u32 %0, %1, %2;" : "=r"(peer_mb[0]) : "r"(mb0), "r"(prk));
        asm("mapa.shared::cluster.u32 %0, %1, %2;" : "=r"(peer_mb[1]) : "r"(mb1), "r"(prk));
    }
    const uint32_t loc_mb[2] = {mb0, mb1};

    const bool writer = (g == 0) && valid;
    const bool arriver = (w == NWARPS - 1) && (l == 0);  // highest warp: wins arbitration

    // ---- gather pipeline prologue: xpv for step 0, token for step 1 ----
    float xpv0 = 0.f, xpv1 = 0.f;
    int tok_n = 0;
    if (writer) {
        int t0 = __ldg(&x[batch]);                        // token for s=0
        float2 xp = *reinterpret_cast<const float2*>(&g_proj[(size_t)t0 * HDIM + row0]);
        xpv0 = xp.x; xpv1 = xp.y;
        tok_n = __ldg(&x[BATCH + batch]);                 // token for s=1
    }

    int p = 0;
    #pragma unroll 1
    for (int s = 0; s < SLEN; s++) {
        // 76-float h chunk loaded once, feeds both rows' dot products.
        const ulonglong2* h2 =
            reinterpret_cast<const ulonglong2*>(hbuf + p * HPAD + g * GCHUNK);
        unsigned long long a00 = 0ull, a01 = 0ull, a10 = 0ull, a11 = 0ull;
        #pragma unroll
        for (int j = 0; j < NJ; j++) {
            ulonglong2 hv = h2[j];
            a00 = fma2(wq0[j].x, hv.x, a00);
            a01 = fma2(wq0[j].y, hv.y, a01);
            a10 = fma2(wq1[j].x, hv.x, a10);
            a11 = fma2(wq1[j].y, hv.y, a11);
        }
        unsigned long long s0, s1;
        asm("add.rn.f32x2 %0, %1, %2;" : "=l"(s0) : "l"(a00), "l"(a01));
        asm("add.rn.f32x2 %0, %1, %2;" : "=l"(s1) : "l"(a10), "l"(a11));
        float sum0 = __uint_as_float((uint32_t)s0) + __uint_as_float((uint32_t)(s0 >> 32));
        float sum1 = __uint_as_float((uint32_t)s1) + __uint_as_float((uint32_t)(s1 >> 32));
        // reduce across the 4 k-groups (lanes strided by 8)
        sum0 += __shfl_xor_sync(0xffffffffu, sum0, 8);
        sum0 += __shfl_xor_sync(0xffffffffu, sum0, 16);
        sum1 += __shfl_xor_sync(0xffffffffu, sum1, 8);
        sum1 += __shfl_xor_sync(0xffffffffu, sum1, 16);

        const int pn = p ^ 1;
        float v0 = 0.f, v1 = 0.f;
        if (writer) {
            v0 = fmaxf(sum0 + xpv0, 0.f);
            v1 = fmaxf(sum1 + xpv1, 0.f);
            unsigned long long pk =
                ((unsigned long long)__float_as_uint(v1) << 32) |
                (unsigned long long)__float_as_uint(v0);
            *reinterpret_cast<unsigned long long*>(&hbuf[pn * HPAD + row0]) = pk;  // local
            asm volatile("st.shared::cluster.b64 [%0], %1;"                        // peer
                         :: "r"(ra[pn]), "l"(pk) : "memory");
        }

        // All reads of hbuf[p] and all peer-stores from this CTA are done.
        __syncthreads();
        const int st = s & 1;                       // ring stage for this step
        if (arriver) {
            asm volatile(
                "mbarrier.arrive.release.cluster.shared::cluster.b64 _, [%0];"
                :: "r"(peer_mb[st]) : "memory");
        }

        // ---- latency shadow: prefetch next gather, drain pooled max ----
        if (writer) {
            float2 xp = *reinterpret_cast<const float2*>(
                &g_proj[(size_t)tok_n * HDIM + row0]);            // for s+1
            xpv0 = xp.x; xpv1 = xp.y;
            int s2 = (s + 2 < SLEN) ? (s + 2) : (SLEN - 1);
            tok_n = __ldg(&x[s2 * BATCH + batch]);                // for s+2
            // relu output >= 0: int-max == float-max on nonnegative floats
            atomicMax((int*)&g_pooled[s * HDIM + row0    ], __float_as_int(v0));
            atomicMax((int*)&g_pooled[s * HDIM + row0 + 1], __float_as_int(v1));
            if (s == SLEN - 1) {
                float2 hv2 = make_float2(v0, v1);
                *reinterpret_cast<float2*>(&out_hid[batch * HDIM + row0]) = hv2;
            }
        }

        // Wait for the peer's arrive on this step's ring stage.
        {
            const uint32_t ph = (uint32_t)((s >> 1) & 1);   // stage phase parity
            uint32_t done;
            asm volatile(
                "{\n\t.reg .pred p;\n\t"
                "mbarrier.try_wait.parity.acquire.cta.shared::cta.b64 p, [%1], %2;\n\t"
                "selp.b32 %0, 1, 0, p;\n\t}"
                : "=r"(done) : "r"(loc_mb[st]), "r"(ph) : "memory");
            if (!done) {
                asm volatile(
                    "{\n\t.reg .pred P1;\n\t"
                    "WAIT_LOOP_%=:\n\t"
                    "mbarrier.try_wait.parity.acquire.cta.shared::cta.b64 P1, [%0], %1, 0x989680;\n\t"
                    "@P1 bra.uni WAIT_DONE_%=;\n\t"
                    "bra.uni WAIT_LOOP_%=;\n\t"
                    "WAIT_DONE_%=:\n\t}"
                    :: "r"(loc_mb[st]), "r"(ph) : "memory");
            }
        }
        p = pn;
    }
}

// ---------------------------------------------------------------------------
// Kernel 3: out[s, c] = pooled[s, :] . W_out[c, :] + b_out[c]   (one warp per s)
// ---------------------------------------------------------------------------
__global__ void out_kernel(const float* __restrict__ W_out,
                           const float* __restrict__ b_out,
                           float* __restrict__ out)
{
    int s = blockIdx.x;
    int l = threadIdx.x;
    float a0 = 0.f, a1 = 0.f;
    for (int h = l; h < HDIM; h += 32) {
        float pv = g_pooled[s * HDIM + h];
        a0 += pv * W_out[h];
        a1 += pv * W_out[HDIM + h];
    }
    #pragma unroll
    for (int o = 16; o > 0; o >>= 1) {
        a0 += __shfl_down_sync(0xffffffffu, a0, o);
        a1 += __shfl_down_sync(0xffffffffu, a1, o);
    }
    if (l == 0) {
        out[s * 2 + 0] = a0 + b_out[0];
        out[s * 2 + 1] = a1 + b_out[1];
    }
}

// ---------------------------------------------------------------------------
// Launch: zero -> proj GEMM -> sequential RNN (64 clusters) -> output GEMM.
// Output layout: out (2048*2 floats) followed by hT (64*300 floats).
// ---------------------------------------------------------------------------
extern "C" void kernel_launch(void* const* d_in, const int* in_sizes, int n_in,
                              void* d_out, int out_size)
{
    (void)in_sizes; (void)n_in; (void)out_size;
    const int*   x     = (const int*)  d_in[0];
    const float* emb   = (const float*)d_in[1];
    const float* W_ih  = (const float*)d_in[2];
    const float* W_hh  = (const float*)d_in[3];
    const float* b_ih  = (const float*)d_in[4];
    const float* b_hh  = (const float*)d_in[5];
    const float* W_out = (const float*)d_in[6];
    const float* b_out = (const float*)d_in[7];

    float* out     = (float*)d_out;
    float* out_hid = out + SLEN * 2;

    zero_pooled_kernel<<<(SLEN * HDIM + 1023) / 1024, 1024>>>();
    proj_kernel<<<dim3((VOCAB + 63) / 64, (HDIM + 63) / 64), 256>>>(emb, W_ih, b_ih, b_hh);
    rnn_kernel<<<BATCH * 2, RNN_THREADS>>>(x, W_hh, out_hid);
    out_kernel<<<SLEN, 32>>>(W_out, b_out, out);
}

// round 14
// speedup vs baseline: 1.0869x; 1.0869x over previous
#include <cuda_runtime.h>
#include <cstdint>

#define VOCAB 50257
#define SLEN  2048
#define BATCH 64
#define HDIM  300
#define HALF  150
#define HPAD2 320            // h buffer: two 160-slot halves (150 rows + 10 pad each)
#define HALFSLOT 160
#define GC2   40             // columns per k-group per half
#define NJH   10             // float4 chunks per half per thread
#define RNN_THREADS 608      // 19 warps x 8 row-slots = 152 >= 150
#define NWARPS 19

// Scratch (device globals are the sanctioned allocation-free scratch).
__device__ float g_proj[(size_t)VOCAB * HDIM];   // ~60.3 MB
__device__ float g_pooled[SLEN * HDIM];

// ---------------------------------------------------------------------------
// packed f32x2 helpers (FFMA2 — only reachable via PTX on sm_103a)
// ---------------------------------------------------------------------------
__device__ __forceinline__ unsigned long long fma2(unsigned long long a,
                                                   unsigned long long b,
                                                   unsigned long long c) {
    unsigned long long d;
    asm("fma.rn.f32x2 %0, %1, %2, %3;" : "=l"(d) : "l"(a), "l"(b), "l"(c));
    return d;
}
__device__ __forceinline__ unsigned long long dup2(float a) {
    unsigned long long d;
    asm("mov.b64 %0, {%1, %1};" : "=l"(d) : "f"(a));
    return d;
}
__device__ __forceinline__ unsigned long long pack2(float lo, float hi) {
    return ((unsigned long long)__float_as_uint(hi) << 32) |
           (unsigned long long)__float_as_uint(lo);
}

// ---------------------------------------------------------------------------
// Kernel 0: zero the pooled max buffer (graph replays must re-zero it)
// ---------------------------------------------------------------------------
__global__ void zero_pooled_kernel() {
    int idx = blockIdx.x * blockDim.x + threadIdx.x;
    if (idx < SLEN * HDIM) g_pooled[idx] = 0.f;
}

// ---------------------------------------------------------------------------
// Kernel 1: proj[v, i] = sum_k emb[v,k] * W_ih[i,k] + b_ih[i] + b_hh[i]
// 64x64 tiled fp32 GEMM, 4x4 micro-tiles via packed f32x2 FMA, KC=16.
// ---------------------------------------------------------------------------
#define PK_KC 16
__global__ void __launch_bounds__(256)
proj_kernel(const float* __restrict__ emb, const float* __restrict__ W_ih,
            const float* __restrict__ b_ih, const float* __restrict__ b_hh)
{
    __shared__ float sA[PK_KC][68];   // [k][m]  (emb tile, transposed)
    __shared__ float sB[PK_KC][68];   // [k][n]  (W_ih tile, transposed)

    const int tid = threadIdx.x;
    const int tx = tid & 15;
    const int ty = tid >> 4;
    const int m0 = blockIdx.x * 64;
    const int n0 = blockIdx.y * 64;

    const int e  = tid * 4;      // each thread loads one float4 per tile
    const int lm = e >> 4;       // 0..63
    const int lk = e & 15;       // 0,4,8,12

    unsigned long long acc2[4][2] = {};

    for (int k0 = 0; k0 < HDIM; k0 += PK_KC) {
        // load A tile (emb rows m0..m0+63)
        {
            int m = m0 + lm;
            int k = k0 + lk;
            float4 v = make_float4(0.f, 0.f, 0.f, 0.f);
            if (m < VOCAB) {
                if (k + 3 < HDIM) {
                    v = *reinterpret_cast<const float4*>(&emb[(size_t)m * HDIM + k]);
                } else {
                    float t0 = (k     < HDIM) ? emb[(size_t)m * HDIM + k    ] : 0.f;
                    float t1 = (k + 1 < HDIM) ? emb[(size_t)m * HDIM + k + 1] : 0.f;
                    float t2 = (k + 2 < HDIM) ? emb[(size_t)m * HDIM + k + 2] : 0.f;
                    float t3 = (k + 3 < HDIM) ? emb[(size_t)m * HDIM + k + 3] : 0.f;
                    v = make_float4(t0, t1, t2, t3);
                }
            }
            sA[lk    ][lm] = v.x;
            sA[lk + 1][lm] = v.y;
            sA[lk + 2][lm] = v.z;
            sA[lk + 3][lm] = v.w;
        }
        // load B tile (W_ih rows n0..n0+63)
        {
            int n = n0 + lm;
            int k = k0 + lk;
            float4 v = make_float4(0.f, 0.f, 0.f, 0.f);
            if (n < HDIM) {
                if (k + 3 < HDIM) {
                    v = *reinterpret_cast<const float4*>(&W_ih[n * HDIM + k]);
                } else {
                    float t0 = (k     < HDIM) ? W_ih[n * HDIM + k    ] : 0.f;
                    float t1 = (k + 1 < HDIM) ? W_ih[n * HDIM + k + 1] : 0.f;
                    float t2 = (k + 2 < HDIM) ? W_ih[n * HDIM + k + 2] : 0.f;
                    float t3 = (k + 3 < HDIM) ? W_ih[n * HDIM + k + 3] : 0.f;
                    v = make_float4(t0, t1, t2, t3);
                }
            }
            sB[lk    ][lm] = v.x;
            sB[lk + 1][lm] = v.y;
            sB[lk + 2][lm] = v.z;
            sB[lk + 3][lm] = v.w;
        }
        __syncthreads();

        #pragma unroll
        for (int kk = 0; kk < PK_KC; kk++) {
            float4 a4 = *reinterpret_cast<const float4*>(&sA[kk][ty * 4]);
            ulonglong2 b2 = *reinterpret_cast<const ulonglong2*>(&sB[kk][tx * 4]);
            float av[4] = {a4.x, a4.y, a4.z, a4.w};
            #pragma unroll
            for (int mi = 0; mi < 4; mi++) {
                unsigned long long am = dup2(av[mi]);
                acc2[mi][0] = fma2(am, b2.x, acc2[mi][0]);
                acc2[mi][1] = fma2(am, b2.y, acc2[mi][1]);
            }
        }
        __syncthreads();
    }

    #pragma unroll
    for (int mi = 0; mi < 4; mi++) {
        int m = m0 + ty * 4 + mi;
        if (m >= VOCAB) continue;
        float r[4];
        r[0] = __uint_as_float((uint32_t)(acc2[mi][0]));
        r[1] = __uint_as_float((uint32_t)(acc2[mi][0] >> 32));
        r[2] = __uint_as_float((uint32_t)(acc2[mi][1]));
        r[3] = __uint_as_float((uint32_t)(acc2[mi][1] >> 32));
        #pragma unroll
        for (int ni = 0; ni < 4; ni++) {
            int n = n0 + tx * 4 + ni;
            if (n < HDIM)
                g_proj[(size_t)m * HDIM + n] = r[ni] + b_ih[n] + b_hh[n];
        }
    }
}

// ---------------------------------------------------------------------------
// Kernel 2: the Elman recurrence — W_hh register-resident, 1 row/thread,
// 19 warps, SPLIT local/remote dot with the mbar wait in the middle, over a
// 2-stage mbarrier ring.
//
// h layout: hbuf[phase][HPAD2=320] = two 160-slot halves; half k holds rows
// [k*150, k*150+150) in slots [k*160, k*160+150); pad slots stay zero.
//
// Per step s:
//   1. local partial: 10 LDS.128 + 20 FMA2 over own CTA's half of h_s
//      (visible since own bar.sync at end of s-1) — overlaps the peer's
//      DSMEM store+arrive transit.
//   2. wait local mbar[s&1] (parity (s>>1)&1) — peer's half of h_s visible.
//   3. remote partial, reduce (2 shfl), v = relu(sum + xpv).
//   4. store v to local hbuf[pn] + peer via st.shared::cluster.
//   5. bar.sync; highest warp lane 0 release-arrives on peer mbar[(s+1)&1].
//   6. shadow: proj/token prefetch, pooled atomicMax.
// Ring safety: a 2nd arrive on a stage requires this CTA to have passed its
// wait on that stage (peer's next-next arrive is gated on our arrive, which
// follows our wait) — double-flip impossible. Prologue arrive seeds stage 0.
// ---------------------------------------------------------------------------
__global__ void __launch_bounds__(RNN_THREADS, 1) __cluster_dims__(2, 1, 1)
rnn_kernel(const int* __restrict__ x, const float* __restrict__ W_hh,
           float* __restrict__ out_hid)
{
    __shared__ float hbuf[2 * HPAD2];                    // double-buffered h
    __shared__ __align__(16) unsigned long long mbar[2]; // 2-stage ring, 1 arrival

    const int tid = threadIdx.x;
    uint32_t rank;
    asm("mov.u32 %0, %%cluster_ctarank;" : "=r"(rank));
    const int batch = blockIdx.x >> 1;

    const int w = tid >> 5;
    const int l = tid & 31;
    const int g = l >> 3;        // k-group 0..3
    const int i = l & 7;         // row-sub 0..7
    const int r_loc = w * 8 + i; // 0..151 (150 valid)
    const bool valid = (r_loc < HALF);
    const int r_use = valid ? r_loc : 0;
    const int row_g = rank * HALF + r_use;   // global output row 0..299

    // ---- load W_hh into registers: 10 local + 10 remote float4 chunks ----
    // local chunk j covers h-slots rank*160 + g*40 + 4j (+0..3)
    //   -> W columns rank*150 + g*40 + 4j (+e), valid while col-offset < 150
    // remote chunk j covers the other half symmetrically.
    ulonglong2 wql[NJH], wqr[NJH];
    {
        const int cb_l = (int)rank * HALF;
        const int cb_r = (int)(rank ^ 1u) * HALF;
        const float* wrow = &W_hh[row_g * HDIM];
        #pragma unroll
        for (int j = 0; j < NJH; j++) {
            float t[4], u[4];
            #pragma unroll
            for (int e2 = 0; e2 < 4; e2++) {
                int o = g * GC2 + 4 * j + e2;
                t[e2] = (o < HALF) ? wrow[cb_l + o] : 0.f;
                u[e2] = (o < HALF) ? wrow[cb_r + o] : 0.f;
            }
            wql[j].x = pack2(t[0], t[1]);
            wql[j].y = pack2(t[2], t[3]);
            wqr[j].x = pack2(u[0], u[1]);
            wqr[j].y = pack2(u[2], u[3]);
        }
    }

    for (int idx = tid; idx < 2 * HPAD2; idx += RNN_THREADS) hbuf[idx] = 0.f;  // h0 = 0

    // SMEM addresses (32-bit) for hbuf and the mbarrier ring.
    uint32_t hbase, mb0;
    asm("{ .reg .u64 t; cvta.to.shared.u64 t, %1; cvt.u32.u64 %0, t; }"
        : "=r"(hbase) : "l"(hbuf));
    asm("{ .reg .u64 t; cvta.to.shared.u64 t, %1; cvt.u32.u64 %0, t; }"
        : "=r"(mb0) : "l"(&mbar[0]));

    if (tid == 0) {
        asm volatile("mbarrier.init.shared.b64 [%0], 1;" :: "r"(mb0) : "memory");
        asm volatile("mbarrier.init.shared.b64 [%0], 1;" :: "r"(mb0 + 8u) : "memory");
    }
    __syncthreads();
    // Both CTAs' hbuf zeros + mbarrier inits must be visible cluster-wide once.
    asm volatile("barrier.cluster.arrive.aligned;" ::: "memory");
    asm volatile("barrier.cluster.wait.aligned;"   ::: "memory");

    // Peer base addresses (offsets within the peer window are linear).
    const uint32_t prk = rank ^ 1u;
    uint32_t ra0, peer_mb0;
    {
        // my row's slot in phase 0: rank*160 + r_use
        uint32_t la0 = hbase + (uint32_t)(rank * HALFSLOT + r_use) * 4u;
        asm("mapa.shared::cluster.u32 %0, %1, %2;" : "=r"(ra0) : "r"(la0), "r"(prk));
        asm("mapa.shared::cluster.u32 %0, %1, %2;" : "=r"(peer_mb0) : "r"(mb0), "r"(prk));
    }

    const bool writer = (g == 0) && valid;
    const bool arriver = (w == NWARPS - 1) && (l == 0);  // highest warp: wins arbitration

    // Prologue arrive: seed stage 0 so the s=0 wait passes (h_0 = zeros).
    if (arriver) {
        asm volatile(
            "mbarrier.arrive.release.cluster.shared::cluster.b64 _, [%0];"
            :: "r"(peer_mb0) : "memory");
    }

    // ---- gather pipeline prologue: xpv for step 0, token for step 1 ----
    float xpv_c = 0.f;
    int tok_n = 0;
    if (writer) {
        int t0 = __ldg(&x[batch]);                        // token for s=0
        xpv_c = __ldg(&g_proj[(size_t)t0 * HDIM + row_g]);
        tok_n = __ldg(&x[BATCH + batch]);                 // token for s=1
    }

    int p = 0;
    #pragma unroll 1
    for (int s = 0; s < SLEN; s++) {
        // ---- phase 1: local-half partial (no peer dependency) ----
        const ulonglong2* hl = reinterpret_cast<const ulonglong2*>(
            hbuf + p * HPAD2 + rank * HALFSLOT + g * GC2);
        unsigned long long acc0 = 0ull, acc1 = 0ull;
        #pragma unroll
        for (int j = 0; j < NJH; j++) {
            ulonglong2 hv = hl[j];
            acc0 = fma2(wql[j].x, hv.x, acc0);
            acc1 = fma2(wql[j].y, hv.y, acc1);
        }

        // ---- phase 2: wait for the peer's half of h_s (ring stage s&1) ----
        {
            const uint32_t mbs = mb0 + (uint32_t)((s & 1) * 8);
            const uint32_t ph = (uint32_t)((s >> 1) & 1);
            uint32_t done;
            asm volatile(
                "{\n\t.reg .pred p;\n\t"
                "mbarrier.try_wait.parity.acquire.cta.shared::cta.b64 p, [%1], %2;\n\t"
                "selp.b32 %0, 1, 0, p;\n\t}"
                : "=r"(done) : "r"(mbs), "r"(ph) : "memory");
            if (!done) {
                asm volatile(
                    "{\n\t.reg .pred P1;\n\t"
                    "WAIT_LOOP_%=:\n\t"
                    "mbarrier.try_wait.parity.acquire.cta.shared::cta.b64 P1, [%0], %1, 0x989680;\n\t"
                    "@P1 bra.uni WAIT_DONE_%=;\n\t"
                    "bra.uni WAIT_LOOP_%=;\n\t"
                    "WAIT_DONE_%=:\n\t}"
                    :: "r"(mbs), "r"(ph) : "memory");
            }
        }

        // ---- phase 3: remote-half partial + reduce ----
        const ulonglong2* hr = reinterpret_cast<const ulonglong2*>(
            hbuf + p * HPAD2 + prk * HALFSLOT + g * GC2);
        #pragma unroll
        for (int j = 0; j < NJH; j++) {
            ulonglong2 hv = hr[j];
            acc0 = fma2(wqr[j].x, hv.x, acc0);
            acc1 = fma2(wqr[j].y, hv.y, acc1);
        }
        unsigned long long accs;
        asm("add.rn.f32x2 %0, %1, %2;" : "=l"(accs) : "l"(acc0), "l"(acc1));
        float sum = __uint_as_float((uint32_t)accs) +
                    __uint_as_float((uint32_t)(accs >> 32));
        sum += __shfl_xor_sync(0xffffffffu, sum, 8);
        sum += __shfl_xor_sync(0xffffffffu, sum, 16);

        const int pn = p ^ 1;
        float v = 0.f;
        if (writer) {
            v = fmaxf(sum + xpv_c, 0.f);
            hbuf[pn * HPAD2 + rank * HALFSLOT + r_use] = v;                // local
            uint32_t rap = ra0 + (uint32_t)(pn * HPAD2 * 4);
            asm volatile("st.shared::cluster.f32 [%0], %1;"                // peer
                         :: "r"(rap), "f"(v) : "memory");
        }

        // All reads of hbuf[p] and all peer-stores from this CTA are done.
        __syncthreads();
        if (arriver) {
            uint32_t pmb = peer_mb0 + (uint32_t)(((s + 1) & 1) * 8);
            asm volatile(
                "mbarrier.arrive.release.cluster.shared::cluster.b64 _, [%0];"
                :: "r"(pmb) : "memory");
        }

        // ---- latency shadow: prefetch next gather, drain pooled max ----
        if (writer) {
            xpv_c = __ldg(&g_proj[(size_t)tok_n * HDIM + row_g]);  // for s+1
            int s2 = (s + 2 < SLEN) ? (s + 2) : (SLEN - 1);
            tok_n = __ldg(&x[s2 * BATCH + batch]);                 // for s+2
            // relu output >= 0: int-max == float-max on nonnegative floats
            atomicMax((int*)&g_pooled[s * HDIM + row_g], __float_as_int(v));
            if (s == SLEN - 1) out_hid[batch * HDIM + row_g] = v;
        }
        p = pn;
    }

    // No CTA may exit while the peer's last-step remote stores/arrives could
    // still be in flight toward this CTA's SMEM.
    asm volatile("barrier.cluster.arrive.aligned;" ::: "memory");
    asm volatile("barrier.cluster.wait.aligned;"   ::: "memory");
}

// ---------------------------------------------------------------------------
// Kernel 3: out[s, c] = pooled[s, :] . W_out[c, :] + b_out[c]   (one warp per s)
// ---------------------------------------------------------------------------
__global__ void out_kernel(const float* __restrict__ W_out,
                           const float* __restrict__ b_out,
                           float* __restrict__ out)
{
    int s = blockIdx.x;
    int l = threadIdx.x;
    float a0 = 0.f, a1 = 0.f;
    for (int h = l; h < HDIM; h += 32) {
        float pv = g_pooled[s * HDIM + h];
        a0 += pv * W_out[h];
        a1 += pv * W_out[HDIM + h];
    }
    #pragma unroll
    for (int o = 16; o > 0; o >>= 1) {
        a0 += __shfl_down_sync(0xffffffffu, a0, o);
        a1 += __shfl_down_sync(0xffffffffu, a1, o);
    }
    if (l == 0) {
        out[s * 2 + 0] = a0 + b_out[0];
        out[s * 2 + 1] = a1 + b_out[1];
    }
}

// ---------------------------------------------------------------------------
// Launch: zero -> proj GEMM -> sequential RNN (64 clusters) -> output GEMM.
// Output layout: out (2048*2 floats) followed by hT (64*300 floats).
// ---------------------------------------------------------------------------
extern "C" void kernel_launch(void* const* d_in, const int* in_sizes, int n_in,
                              void* d_out, int out_size)
{
    (void)in_sizes; (void)n_in; (void)out_size;
    const int*   x     = (const int*)  d_in[0];
    const float* emb   = (const float*)d_in[1];
    const float* W_ih  = (const float*)d_in[2];
    const float* W_hh  = (const float*)d_in[3];
    const float* b_ih  = (const float*)d_in[4];
    const float* b_hh  = (const float*)d_in[5];
    const float* W_out = (const float*)d_in[6];
    const float* b_out = (const float*)d_in[7];

    float* out     = (float*)d_out;
    float* out_hid = out + SLEN * 2;

    zero_pooled_kernel<<<(SLEN * HDIM + 1023) / 1024, 1024>>>();
    proj_kernel<<<dim3((VOCAB + 63) / 64, (HDIM + 63) / 64), 256>>>(emb, W_ih, b_ih, b_hh);
    rnn_kernel<<<BATCH * 2, RNN_THREADS>>>(x, W_hh, out_hid);
    out_kernel<<<SLEN, 32>>>(W_out, b_out, out);
}